// round 8
// baseline (speedup 1.0000x reference)
#include <cuda_runtime.h>
#include <cstdint>

#define N_B   4
#define DIM   32
#define VG    35937                    /* 33^3 */
#define NVOX  131072                   /* 4*32^3 */
#define FTOT  1572864                  /* NVOX*12 faces */
#define F4    (FTOT/4)                 /* 393216 float4 per segment */
#define NVERT (N_B*VG)                 /* 143748 */

/* flat float32 output offsets (reference tuple order, flattened + concat) */
#define OFF_VC    0
#define OFF_FC    4
#define OFF_VPOS  8
#define OFF_USED  (OFF_VPOS + NVERT*3)          /* 431252   */
#define OFF_EIDX  (OFF_USED + NVERT)            /* 575000   */
#define OFF_FACES (OFF_EIDX + 12*FTOT)          /* 19449368 */
#define OFF_FMASK (OFF_FACES + 3*FTOT)          /* 24167960 */
#define OFF_EMASK (OFF_FMASK + FTOT)            /* 25740824 */

/* kernel 1 (no g_occ reads): occ | faces | edges */
#define OB 512                         /* occ:   512*256 = NVOX            */
#define FB 1536                        /* faces: 1536*256*3 = 3*FTOT/4 f4  */
#define EB 1536                        /* edges: 1536*256 = F4 threads     */
#define G1 (OB+FB+EB)
/* kernel 2 (g_occ consumers): counts | masks | verts */
#define CB 4
#define MB 1536
#define VB 562                         /* 562*256 >= 143748 */
#define G2 (CB+MB+VB)

/* occupancy bitmask: 32 x-bits per word, [n][z][y] -> 16 KB */
__device__ uint32_t g_occ[N_B][DIM][DIM];

/* vertex-id offsets in the 33^3 grid, j-major flat: TF[j*3+c], j=2*face+tri.
   VO(dz,dy,dx) = dz*1089 + dy*33 + dx, derived from QUAD_OFFS+TRI_SEL. */
__constant__ int c_TF[36] = {
       0,    1,   33,     1,   33,   34,    /* f0 -z */
    1089, 1090, 1122,  1090, 1122, 1123,    /* f1 +z */
    1089, 1090,    0,  1090,    0,    1,    /* f2 -y */
      33,   34, 1122,    34, 1122, 1123,    /* f3 +y */
    1089,    0, 1122,     0, 1122,   33,    /* f4 -x */
       1, 1090,   34,  1090,   34, 1123     /* f5 +x */
};

__device__ __forceinline__ int vox_base(int vox, int& n, int& z, int& y, int& x) {
    x = vox & 31; y = (vox >> 5) & 31; z = (vox >> 10) & 31; n = vox >> 15;
    return n * VG + z * 1089 + y * 33 + x;
}

/* 6 exposure bits (f0..f5) for voxel (n,z,y,x) — reads only g_occ */
__device__ __forceinline__ unsigned expo_bits(int n, int z, int y, int x) {
    uint32_t wc = g_occ[n][z][y];
    if (!((wc >> x) & 1u)) return 0u;
    uint32_t wzm = (z > 0)  ? g_occ[n][z-1][y] : 0u;
    uint32_t wzp = (z < 31) ? g_occ[n][z+1][y] : 0u;
    uint32_t wym = (y > 0)  ? g_occ[n][z][y-1] : 0u;
    uint32_t wyp = (y < 31) ? g_occ[n][z][y+1] : 0u;
    unsigned e = 0;
    e |= ((~(wzm >> x)) & 1u) << 0;
    e |= ((~(wzp >> x)) & 1u) << 1;
    e |= ((~(wym >> x)) & 1u) << 2;
    e |= ((~(wyp >> x)) & 1u) << 3;
    unsigned xm = (x > 0)  ? ((wc >> (x-1)) & 1u) : 0u;
    unsigned xp = (x < 31) ? ((wc >> (x+1)) & 1u) : 0u;
    e |= (xm ^ 1u) << 4;
    e |= (xp ^ 1u) << 5;
    return e;
}

/* ------------------------------------------------------------------ */
/* kernel 1: occ build + faces + edge_index (no g_occ reads anywhere) */
__global__ void __launch_bounds__(256) k_flood(const float* __restrict__ p,
                                               float* __restrict__ out) {
    __shared__ float s_tf[36];
    int tid = threadIdx.x;
    if (tid < 36) s_tf[tid] = (float)c_TF[tid];
    int b = blockIdx.x;

    if (b < OB) {
        /* ---- occ build: one thread per voxel, ballot -> bitmask word */
        int g = b * 256 + tid;
        float v = p[g];                                  /* linear (n,z,y,x) */
        unsigned m = __ballot_sync(0xffffffffu, v > 0.5f);
        if ((tid & 31) == 0)
            reinterpret_cast<uint32_t*>(g_occ)[g >> 5] = m;
        return;
    }
    __syncthreads();   /* s_tf ready */
    b -= OB;

    if (b < FB) {
        /* ---- faces: 3 coalesced float4 per thread (f4 #t, t=vox*9+q) */
        int t0 = b * 768 + tid;
        float4* dF = (float4*)(out + OFF_FACES);
        #pragma unroll
        for (int k = 0; k < 3; k++) {
            int t   = t0 + k * 256;
            int vox = t / 9;
            int q   = t - vox * 9;
            int n, z, y, x;
            float bf = (float)vox_base(vox, n, z, y, x);
            int i0 = 4 * q;
            dF[t] = make_float4(bf + s_tf[i0], bf + s_tf[i0+1],
                                bf + s_tf[i0+2], bf + s_tf[i0+3]);
        }
        return;
    }
    b -= FB;
    {
        /* ---- edge_index: thread t = vox*3+q; 3 distinct contents, each
           replicated into 4 of the 12 segments, all stores coalesced   */
        int t   = b * 256 + tid;
        int vox = t / 3;
        int q   = t - vox * 3;
        int n, z, y, x;
        float bf = (float)vox_base(vox, n, z, y, x);
        int j0 = 4 * q;
        float4 v0 = make_float4(bf + s_tf[3*j0+0], bf + s_tf[3*(j0+1)+0],
                                bf + s_tf[3*(j0+2)+0], bf + s_tf[3*(j0+3)+0]);
        float4 v1 = make_float4(bf + s_tf[3*j0+1], bf + s_tf[3*(j0+1)+1],
                                bf + s_tf[3*(j0+2)+1], bf + s_tf[3*(j0+3)+1]);
        float4 v2 = make_float4(bf + s_tf[3*j0+2], bf + s_tf[3*(j0+1)+2],
                                bf + s_tf[3*(j0+2)+2], bf + s_tf[3*(j0+3)+2]);
        float4* E = (float4*)(out + OFF_EIDX);
        /* row0 sels: 0,1,0,1,2,2  row1 sels: 1,2,2,0,1,0 */
        E[ 0*F4 + t] = v0;  E[ 2*F4 + t] = v0;  E[ 9*F4 + t] = v0;  E[11*F4 + t] = v0;
        E[ 1*F4 + t] = v1;  E[ 3*F4 + t] = v1;  E[ 6*F4 + t] = v1;  E[10*F4 + t] = v1;
        E[ 4*F4 + t] = v2;  E[ 5*F4 + t] = v2;  E[ 7*F4 + t] = v2;  E[ 8*F4 + t] = v2;
    }
}

/* ------------------------------------------------------------------ */
/* kernel 2: counts + masks + verts (launch boundary = fence for g_occ) */
__global__ void __launch_bounds__(256) k_post(float* __restrict__ out) {
    int tid = threadIdx.x;
    int b = blockIdx.x;

    if (b < CB) {
        /* ---- counts block for batch n: copy g_occ[n] (4 KB) to smem,
           then reduce face_count and vert_count; direct writes.       */
        int n = b;
        __shared__ uint32_t s_occ[1024];          /* [z*32+y] -> x bits */
        __shared__ int red_f[8], red_v[8];
        int warp = tid >> 5, lane = tid & 31;
        for (int w = tid; w < 1024; w += 256)
            s_occ[w] = g_occ[n][0][w];            /* flat [z*32+y]      */
        __syncthreads();

        int fc = 0;
        for (int v = tid; v < 32768; v += 256) {
            int x = v & 31, y = (v >> 5) & 31, z = v >> 10;
            uint32_t wc = s_occ[z * 32 + y];
            if ((wc >> x) & 1u) {
                int nb = 0;
                nb += (z > 0)  ? (int)((s_occ[(z-1)*32 + y] >> x) & 1u) : 0;
                nb += (z < 31) ? (int)((s_occ[(z+1)*32 + y] >> x) & 1u) : 0;
                nb += (y > 0)  ? (int)((s_occ[z*32 + y-1] >> x) & 1u) : 0;
                nb += (y < 31) ? (int)((s_occ[z*32 + y+1] >> x) & 1u) : 0;
                nb += (x > 0)  ? (int)((wc >> (x-1)) & 1u) : 0;
                nb += (x < 31) ? (int)((wc >> (x+1)) & 1u) : 0;
                fc += 2 * (6 - nb);
            }
        }
        int vc = 0;
        for (int idx = tid; idx < VG; idx += 256) {
            int gz = idx / 1089; int r2 = idx - gz * 1089;
            int gy = r2 / 33;    int gx = r2 - gy * 33;
            unsigned anyb = 0u, allb = 1u;
            #pragma unroll
            for (int dz = 0; dz < 2; dz++)
            #pragma unroll
            for (int dy = 0; dy < 2; dy++) {
                int z = gz - dz, y = gy - dy;
                uint32_t w = ((unsigned)z < 32u && (unsigned)y < 32u)
                           ? s_occ[z*32 + y] : 0u;
                unsigned b0 = (gx < 32) ? ((w >> gx) & 1u) : 0u;
                unsigned b1 = (gx >= 1) ? ((w >> (gx-1)) & 1u) : 0u;
                anyb |= b0 | b1;
                allb &= b0 & b1;
            }
            vc += (int)(anyb & (allb ^ 1u));
        }
        #pragma unroll
        for (int o = 16; o > 0; o >>= 1) {
            fc += __shfl_down_sync(0xffffffffu, fc, o);
            vc += __shfl_down_sync(0xffffffffu, vc, o);
        }
        if (lane == 0) { red_f[warp] = fc; red_v[warp] = vc; }
        __syncthreads();
        if (tid == 0) {
            int tf = 0, tv = 0;
            #pragma unroll
            for (int w = 0; w < 8; w++) { tf += red_f[w]; tv += red_v[w]; }
            out[OFF_FC + n] = (float)tf;
            out[OFF_VC + n] = (float)tv;
        }
        return;
    }
    b -= CB;
    if (b < MB) {
        /* ---- masks: face_mask + 6 identical edge_mask segments */
        int t   = b * 256 + tid;
        int vox = t / 3;
        int q   = t - vox * 3;
        int n, z, y, x;
        (void)vox_base(vox, n, z, y, x);
        unsigned e = expo_bits(n, z, y, x);
        float a0 = (float)((e >> (2*q    )) & 1u);
        float a1 = (float)((e >> (2*q + 1)) & 1u);
        float4 m = make_float4(a0, a0, a1, a1);
        ((float4*)(out + OFF_FMASK))[t] = m;
        float4* EM = (float4*)(out + OFF_EMASK);
        #pragma unroll
        for (int s = 0; s < 6; s++) EM[s*F4 + t] = m;
        return;
    }
    b -= MB;
    {
        /* ---- vertices: used / vpos */
        int idx = b * 256 + tid;
        if (idx < NVERT) {
            int n  = idx / VG;
            int r  = idx - n * VG;
            int gz = r / 1089;  int r2 = r - gz * 1089;
            int gy = r2 / 33;   int gx = r2 - gy * 33;

            unsigned anyb = 0u, allb = 1u;
            #pragma unroll
            for (int dz = 0; dz < 2; dz++)
            #pragma unroll
            for (int dy = 0; dy < 2; dy++) {
                int z = gz - dz, y = gy - dy;
                uint32_t w = ((unsigned)z < 32u && (unsigned)y < 32u)
                           ? g_occ[n][z][y] : 0u;
                unsigned b0 = (gx < 32) ? ((w >> gx) & 1u) : 0u;
                unsigned b1 = (gx >= 1) ? ((w >> (gx - 1)) & 1u) : 0u;
                anyb |= b0 | b1;
                allb &= b0 & b1;
            }
            unsigned used = anyb & (allb ^ 1u);
            out[OFF_USED + idx] = (float)used;
            float m = used ? 1.0f : 0.0f;
            out[OFF_VPOS + 3*idx + 0] = m * ((float)gz - 0.5f);
            out[OFF_VPOS + 3*idx + 1] = m * ((float)gy - 0.5f);
            out[OFF_VPOS + 3*idx + 2] = m * ((float)gx - 0.5f);
        }
    }
}

/* ------------------------------------------------------------------ */
extern "C" void kernel_launch(void* const* d_in, const int* in_sizes, int n_in,
                              void* d_out, int out_size) {
    const float* p = (const float*)d_in[0];
    float* out = (float*)d_out;
    (void)in_sizes; (void)n_in; (void)out_size;
    k_flood<<<G1, 256>>>(p, out);
    k_post <<<G2, 256>>>(out);
}

// round 9
// speedup vs baseline: 1.6028x; 1.6028x over previous
#include <cuda_runtime.h>
#include <cstdint>

#define N_B   4
#define DIM   32
#define VG    35937                    /* 33^3 */
#define NVOX  131072                   /* 4*32^3 */
#define FTOT  1572864                  /* NVOX*12 faces */
#define F4    (FTOT/4)                 /* 393216 float4 per segment */
#define NVERT (N_B*VG)                 /* 143748 */

/* flat float32 output offsets (reference tuple order, flattened + concat) */
#define OFF_VC    0
#define OFF_FC    4
#define OFF_VPOS  8
#define OFF_USED  (OFF_VPOS + NVERT*3)          /* 431252   */
#define OFF_EIDX  (OFF_USED + NVERT)            /* 575000   */
#define OFF_FACES (OFF_EIDX + 12*FTOT)          /* 19449368 */
#define OFF_FMASK (OFF_FACES + 3*FTOT)          /* 24167960 */
#define OFF_EMASK (OFF_FMASK + FTOT)            /* 25740824 */

/* block-range dispatch (R5 order): faces | edges | masks | verts */
#define FB 1536                        /* faces:  1536*256*3 = 3*FTOT/4 f4 */
#define EB 1536                        /* edges:  1536*256 = F4 threads    */
#define MB 1536                        /* masks                            */
#define VB 562                         /* verts:  562*256 >= 143748        */
#define GB (FB+EB+MB+VB)

/* occupancy bitmask: 32 x-bits per word, [n][z][y] -> 16 KB, cache-hot */
__device__ uint32_t g_occ[N_B][DIM][DIM];

/* vertex-id offsets in the 33^3 grid, j-major flat: TF[j*3+c], j=2*face+tri.
   VO(dz,dy,dx) = dz*1089 + dy*33 + dx, derived from QUAD_OFFS+TRI_SEL. */
__constant__ int c_TF[36] = {
       0,    1,   33,     1,   33,   34,    /* f0 -z */
    1089, 1090, 1122,  1090, 1122, 1123,    /* f1 +z */
    1089, 1090,    0,  1090,    0,    1,    /* f2 -y */
      33,   34, 1122,    34, 1122, 1123,    /* f3 +y */
    1089,    0, 1122,     0, 1122,   33,    /* f4 -x */
       1, 1090,   34,  1090,   34, 1123     /* f5 +x */
};

/* ------------------------------------------------------------------ */
__global__ void k_occ(const float* __restrict__ p, float* __restrict__ out) {
    int tid = blockIdx.x * blockDim.x + threadIdx.x;      /* < NVOX */
    if (tid < 8) out[tid] = 0.0f;                          /* zero count slots */
    float v = p[tid];                                      /* linear == (n,z,y,x) */
    unsigned m = __ballot_sync(0xffffffffu, v > 0.5f);     /* lane == x */
    if ((tid & 31) == 0)
        reinterpret_cast<uint32_t*>(g_occ)[tid >> 5] = m;
    cudaTriggerProgrammaticLaunchCompletion();
}

/* 6 exposure bits (f0..f5) for voxel (n,z,y,x) — reads only g_occ */
__device__ __forceinline__ unsigned expo_bits(int n, int z, int y, int x) {
    uint32_t wc = g_occ[n][z][y];
    if (!((wc >> x) & 1u)) return 0u;
    uint32_t wzm = (z > 0)  ? g_occ[n][z-1][y] : 0u;
    uint32_t wzp = (z < 31) ? g_occ[n][z+1][y] : 0u;
    uint32_t wym = (y > 0)  ? g_occ[n][z][y-1] : 0u;
    uint32_t wyp = (y < 31) ? g_occ[n][z][y+1] : 0u;
    unsigned e = 0;
    e |= ((~(wzm >> x)) & 1u) << 0;
    e |= ((~(wzp >> x)) & 1u) << 1;
    e |= ((~(wym >> x)) & 1u) << 2;
    e |= ((~(wyp >> x)) & 1u) << 3;
    unsigned xm = (x > 0)  ? ((wc >> (x-1)) & 1u) : 0u;
    unsigned xp = (x < 31) ? ((wc >> (x+1)) & 1u) : 0u;
    e |= (xm ^ 1u) << 4;
    e |= (xp ^ 1u) << 5;
    return e;
}

__device__ __forceinline__ int vox_base(int vox, int& n, int& z, int& y, int& x) {
    x = vox & 31; y = (vox >> 5) & 31; z = (vox >> 10) & 31; n = vox >> 15;
    return n * VG + z * 1089 + y * 33 + x;
}

/* ------------------------------------------------------------------ */
__global__ void __launch_bounds__(256) k_main(float* __restrict__ out) {
    __shared__ float s_tf[36];
    __shared__ int   sc[N_B];
    int tid = threadIdx.x;
    if (tid < 36) s_tf[tid] = (float)c_TF[tid];
    if (tid < N_B) sc[tid] = 0;
    __syncthreads();

    int b = blockIdx.x;

    if (b < FB) {
        /* ---- faces: 3 coalesced float4 per thread (f4 #t, t=vox*9+q).
           No g_occ dependency — runs concurrently with k_occ under PDL. */
        int t0 = b * 768 + tid;
        float4* dF = (float4*)(out + OFF_FACES);
        #pragma unroll
        for (int k = 0; k < 3; k++) {
            int t   = t0 + k * 256;
            int vox = t / 9;
            int q   = t - vox * 9;
            int n, z, y, x;
            float bf = (float)vox_base(vox, n, z, y, x);
            int i0 = 4 * q;
            dF[t] = make_float4(bf + s_tf[i0], bf + s_tf[i0+1],
                                bf + s_tf[i0+2], bf + s_tf[i0+3]);
        }
        return;
    }
    if (b < FB + EB) {
        /* ---- edge_index: thread t = vox*3+q; 3 distinct contents, each
           replicated into 4 of the 12 segments, all stores coalesced.
           No g_occ dependency.                                          */
        int t   = (b - FB) * 256 + tid;
        int vox = t / 3;
        int q   = t - vox * 3;
        int n, z, y, x;
        float bf = (float)vox_base(vox, n, z, y, x);
        int j0 = 4 * q;                      /* triangles j0..j0+3 */
        float4 v0 = make_float4(bf + s_tf[3*j0+0], bf + s_tf[3*(j0+1)+0],
                                bf + s_tf[3*(j0+2)+0], bf + s_tf[3*(j0+3)+0]);
        float4 v1 = make_float4(bf + s_tf[3*j0+1], bf + s_tf[3*(j0+1)+1],
                                bf + s_tf[3*(j0+2)+1], bf + s_tf[3*(j0+3)+1]);
        float4 v2 = make_float4(bf + s_tf[3*j0+2], bf + s_tf[3*(j0+1)+2],
                                bf + s_tf[3*(j0+2)+2], bf + s_tf[3*(j0+3)+2]);
        float4* E = (float4*)(out + OFF_EIDX);
        /* row0 sels: 0,1,0,1,2,2  row1 sels: 1,2,2,0,1,0 */
        E[ 0*F4 + t] = v0;  E[ 2*F4 + t] = v0;  E[ 9*F4 + t] = v0;  E[11*F4 + t] = v0;
        E[ 1*F4 + t] = v1;  E[ 3*F4 + t] = v1;  E[ 6*F4 + t] = v1;  E[10*F4 + t] = v1;
        E[ 4*F4 + t] = v2;  E[ 5*F4 + t] = v2;  E[ 7*F4 + t] = v2;  E[ 8*F4 + t] = v2;
        return;
    }
    if (b < FB + EB + MB) {
        /* ---- masks: face_mask + 6 identical edge_mask segments.
           Reads g_occ + atomics on k_occ-zeroed slots -> PDL sync first. */
        cudaGridDependencySynchronize();
        int t   = (b - FB - EB) * 256 + tid;
        int vox = t / 3;
        int q   = t - vox * 3;
        int n, z, y, x;
        (void)vox_base(vox, n, z, y, x);
        unsigned e = expo_bits(n, z, y, x);
        float a0 = (float)((e >> (2*q    )) & 1u);
        float a1 = (float)((e >> (2*q + 1)) & 1u);
        float4 m = make_float4(a0, a0, a1, a1);
        ((float4*)(out + OFF_FMASK))[t] = m;
        float4* EM = (float4*)(out + OFF_EMASK);
        #pragma unroll
        for (int s = 0; s < 6; s++) EM[s*F4 + t] = m;

        /* face counts: only q==0 lane of each voxel contributes 2*popc(e);
           n is warp-uniform (phase thread-count boundaries divide 98304) */
        int cnt = (q == 0) ? 2 * __popc(e) : 0;
        #pragma unroll
        for (int o = 16; o > 0; o >>= 1) cnt += __shfl_down_sync(0xffffffffu, cnt, o);
        if ((tid & 31) == 0 && cnt)
            atomicAdd(&out[OFF_FC + n], (float)cnt);
        return;
    }
    /* ---- vertices: used / vpos / vert_counts (g_occ reader -> sync) */
    {
        cudaGridDependencySynchronize();
        int idx = (b - FB - EB - MB) * 256 + tid;
        if (idx < NVERT) {
            int n  = idx / VG;
            int r  = idx - n * VG;
            int gz = r / 1089;  int r2 = r - gz * 1089;
            int gy = r2 / 33;   int gx = r2 - gy * 33;

            unsigned anyb = 0u, allb = 1u;
            #pragma unroll
            for (int dz = 0; dz < 2; dz++)
            #pragma unroll
            for (int dy = 0; dy < 2; dy++) {
                int z = gz - dz, y = gy - dy;
                uint32_t w = ((unsigned)z < 32u && (unsigned)y < 32u)
                           ? g_occ[n][z][y] : 0u;
                unsigned b0 = (gx < 32) ? ((w >> gx) & 1u) : 0u;
                unsigned b1 = (gx >= 1) ? ((w >> (gx - 1)) & 1u) : 0u;
                anyb |= b0 | b1;
                allb &= b0 & b1;
            }
            unsigned used = anyb & (allb ^ 1u);
            out[OFF_USED + idx] = (float)used;
            float m = used ? 1.0f : 0.0f;
            out[OFF_VPOS + 3*idx + 0] = m * ((float)gz - 0.5f);
            out[OFF_VPOS + 3*idx + 1] = m * ((float)gy - 0.5f);
            out[OFF_VPOS + 3*idx + 2] = m * ((float)gx - 0.5f);
            if (used) atomicAdd(&sc[n], 1);
        }
        __syncthreads();
        if (tid < N_B && sc[tid])
            atomicAdd(&out[OFF_VC + tid], (float)sc[tid]);
    }
}

/* ------------------------------------------------------------------ */
extern "C" void kernel_launch(void* const* d_in, const int* in_sizes, int n_in,
                              void* d_out, int out_size) {
    const float* p = (const float*)d_in[0];
    float* out = (float*)d_out;
    (void)in_sizes; (void)n_in; (void)out_size;

    k_occ<<<NVOX / 256, 256>>>(p, out);

    /* k_main with programmatic dependent launch: face/edge blocks start
       while k_occ is still running; mask/vert blocks gridDependencySync. */
    cudaLaunchConfig_t cfg = {};
    cfg.gridDim  = dim3(GB);
    cfg.blockDim = dim3(256);
    cfg.stream   = 0;
    cudaLaunchAttribute attr[1];
    attr[0].id = cudaLaunchAttributeProgrammaticStreamSerialization;
    attr[0].val.programmaticStreamSerializationAllowed = 1;
    cfg.attrs    = attr;
    cfg.numAttrs = 1;
    cudaLaunchKernelEx(&cfg, k_main, out);
}